// round 13
// baseline (speedup 1.0000x reference)
#include <cuda_runtime.h>
#include <cuda_fp16.h>
#include <stdint.h>

// Problem constants
#define EMB   1024
#define HN    16
#define HD    64
#define BATCH 2
#define SEQ   2048
#define ROWS  (BATCH*SEQ)   // 4096
#define NQKV  (3*EMB)       // 3072

// ---------------- scratch (device globals: no cudaMalloc allowed) ----------------
__device__ __align__(16) __half g_x   [ROWS*EMB];          // 8 MB
__device__ __align__(16) __half g_wqkv[EMB*NQKV];          // 6 MB
__device__ __align__(16) __half g_wo  [EMB*EMB];           // 2 MB
__device__ __align__(16) __half g_q   [BATCH*HN*SEQ*HD];   // 8 MB (pre-scaled by 0.125)
__device__ __align__(16) __half g_k   [BATCH*HN*SEQ*HD];   // 8 MB
__device__ __align__(16) __half g_v   [BATCH*HN*SEQ*HD];   // 8 MB
__device__ __align__(16) __half g_attn[ROWS*EMB];          // 8 MB  [b*S+s][h*64+d]

// ---------------- helpers ----------------
__device__ __forceinline__ uint32_t sptr(const void* p) {
    return (uint32_t)__cvta_generic_to_shared(p);
}
__device__ __forceinline__ void ldsm4(uint32_t& r0, uint32_t& r1, uint32_t& r2, uint32_t& r3, uint32_t a) {
    asm volatile("ldmatrix.sync.aligned.m8n8.x4.shared.b16 {%0,%1,%2,%3},[%4];"
                 : "=r"(r0), "=r"(r1), "=r"(r2), "=r"(r3) : "r"(a));
}
__device__ __forceinline__ void ldsm4t(uint32_t& r0, uint32_t& r1, uint32_t& r2, uint32_t& r3, uint32_t a) {
    asm volatile("ldmatrix.sync.aligned.m8n8.x4.trans.shared.b16 {%0,%1,%2,%3},[%4];"
                 : "=r"(r0), "=r"(r1), "=r"(r2), "=r"(r3) : "r"(a));
}
__device__ __forceinline__ void mma16816(float* c,
                                         uint32_t a0, uint32_t a1, uint32_t a2, uint32_t a3,
                                         uint32_t b0, uint32_t b1) {
    asm volatile("mma.sync.aligned.m16n8k16.row.col.f32.f16.f16.f32 "
                 "{%0,%1,%2,%3},{%4,%5,%6,%7},{%8,%9},{%0,%1,%2,%3};"
                 : "+f"(c[0]), "+f"(c[1]), "+f"(c[2]), "+f"(c[3])
                 : "r"(a0), "r"(a1), "r"(a2), "r"(a3), "r"(b0), "r"(b1));
}
__device__ __forceinline__ uint32_t packh2(float lo, float hi) {
    __half2 h = __floats2half2_rn(lo, hi);
    return *reinterpret_cast<uint32_t*>(&h);
}

// ---------------- fp32 -> fp16 conversion of x, W_qkv, W_o (one fused kernel) ----------------
__global__ void cvt_all(const float4* __restrict__ x,
                        const float4* __restrict__ wq,
                        const float4* __restrict__ wo) {
    const int NX = ROWS*EMB/4;      // 1048576
    const int NW = EMB*NQKV/4;      // 786432
    const int NO = EMB*EMB/4;       // 262144
    int i = blockIdx.x * blockDim.x + threadIdx.x;
    float4 v; __half2* d;
    if (i < NX)           { v = x[i];          d = (__half2*)g_x    + 2*(size_t)i; }
    else if (i < NX+NW)   { int j = i-NX;      v = wq[j]; d = (__half2*)g_wqkv + 2*(size_t)j; }
    else                  { int j = i-NX-NW;   if (j >= NO) return;
                            v = wo[j];         d = (__half2*)g_wo   + 2*(size_t)j; }
    d[0] = __floats2half2_rn(v.x, v.y);
    d[1] = __floats2half2_rn(v.z, v.w);
}

// ---------------- generic 128x128-tile GEMM (M=4096, K=1024) ----------------
// epi==0: C = x @ W_qkv + b_qkv, scattered into g_q (scaled 0.125) / g_k / g_v  (fp16)
// epi==1: C = g_attn @ W_o + b_o, written as fp32 to outF
__global__ __launch_bounds__(256) void gemm_kernel(const float* __restrict__ bias,
                                                   float* __restrict__ outF,
                                                   int N, int epi) {
    const __half* __restrict__ A  = epi ? g_attn : g_x;
    const __half* __restrict__ Bw = epi ? g_wo   : g_wqkv;

    __shared__ __align__(16) __half As[128][72];
    __shared__ __align__(16) __half Bs[64][136];

    const int tid  = threadIdx.x;
    const int lane = tid & 31;
    const int warp = tid >> 5;
    const int bm = blockIdx.y * 128;
    const int bn = blockIdx.x * 128;
    const int wm = (warp >> 1) * 32;   // 4 warps over M
    const int wn = (warp & 1) * 64;    // 2 warps over N

    float acc[2][8][4];
#pragma unroll
    for (int mt = 0; mt < 2; mt++)
#pragma unroll
        for (int nt = 0; nt < 8; nt++)
#pragma unroll
            for (int e = 0; e < 4; e++) acc[mt][nt][e] = 0.f;

    for (int kk = 0; kk < 1024; kk += 64) {
#pragma unroll
        for (int i = 0; i < 4; i++) {            // A tile: 128x64
            int idx = tid + i * 256;
            int r = idx >> 3, c = (idx & 7) * 8;
            *(uint4*)&As[r][c] = *(const uint4*)(A + (size_t)(bm + r) * 1024 + kk + c);
        }
#pragma unroll
        for (int i = 0; i < 4; i++) {            // B tile: 64x128
            int idx = tid + i * 256;
            int r = idx >> 4, c = (idx & 15) * 8;
            *(uint4*)&Bs[r][c] = *(const uint4*)(Bw + (size_t)(kk + r) * N + bn + c);
        }
        __syncthreads();

#pragma unroll
        for (int j = 0; j < 4; j++) {            // 4 k16 steps
            uint32_t a[2][4];
#pragma unroll
            for (int mt = 0; mt < 2; mt++)
                ldsm4(a[mt][0], a[mt][1], a[mt][2], a[mt][3],
                      sptr(&As[wm + mt*16 + (lane & 15)][j*16 + (lane >> 4) * 8]));
            uint32_t b[8][2];
#pragma unroll
            for (int tp = 0; tp < 4; tp++)
                ldsm4t(b[2*tp][0], b[2*tp][1], b[2*tp+1][0], b[2*tp+1][1],
                       sptr(&Bs[j*16 + (lane & 7) + ((lane >> 3) & 1) * 8]
                              [wn + tp*16 + (lane >> 4) * 8]));
#pragma unroll
            for (int mt = 0; mt < 2; mt++)
#pragma unroll
                for (int nt = 0; nt < 8; nt++)
                    mma16816(acc[mt][nt], a[mt][0], a[mt][1], a[mt][2], a[mt][3],
                             b[nt][0], b[nt][1]);
        }
        __syncthreads();
    }

    // epilogue
#pragma unroll
    for (int mt = 0; mt < 2; mt++)
#pragma unroll
        for (int nt = 0; nt < 8; nt++)
#pragma unroll
            for (int h2 = 0; h2 < 2; h2++) {
                int gr = bm + wm + mt*16 + (lane >> 2) + h2*8;
                int gc = bn + wn + nt*8 + (lane & 3) * 2;
                float v0 = acc[mt][nt][h2*2 + 0] + bias[gc];
                float v1 = acc[mt][nt][h2*2 + 1] + bias[gc + 1];
                if (epi == 0) {
                    int sec = gc >> 10;         // 0:q 1:k 2:v
                    int e   = gc & 1023;
                    if (sec == 0) { v0 *= 0.125f; v1 *= 0.125f; }  // 1/sqrt(64)
                    __half* dst = (sec == 0) ? g_q : (sec == 1 ? g_k : g_v);
                    int b = gr >> 11, s = gr & 2047;
                    int h = e >> 6,  d = e & 63;
                    size_t off = ((size_t)((b * HN + h) * SEQ + s)) * HD + d;
                    *(__half2*)(dst + off) = __floats2half2_rn(v0, v1);
                } else {
                    *(float2*)(outF + (size_t)gr * N + gc) = make_float2(v0, v1);
                }
            }
}

// ---------------- causal flash attention (FA2-style, 64 q rows / block) ----------------
__global__ __launch_bounds__(128) void flash_kernel() {
    const int qt = blockIdx.x;     // q tile (64 rows)
    const int bh = blockIdx.y;     // b*HN + h
    const __half* __restrict__ qp = g_q + (size_t)bh * SEQ * HD;
    const __half* __restrict__ kp = g_k + (size_t)bh * SEQ * HD;
    const __half* __restrict__ vp = g_v + (size_t)bh * SEQ * HD;

    __shared__ __align__(16) __half Qs[64][72];
    __shared__ __align__(16) __half Ks[64][72];
    __shared__ __align__(16) __half Vs[64][72];

    const int tid  = threadIdx.x;
    const int lane = tid & 31;
    const int warp = tid >> 5;     // each warp: 16 q rows

#pragma unroll
    for (int i = 0; i < 4; i++) {
        int idx = tid + i * 128;
        int r = idx >> 3, c = (idx & 7) * 8;
        *(uint4*)&Qs[r][c] = *(const uint4*)(qp + (size_t)(qt*64 + r) * 64 + c);
    }

    float oacc[8][4];
#pragma unroll
    for (int t = 0; t < 8; t++)
#pragma unroll
        for (int e = 0; e < 4; e++) oacc[t][e] = 0.f;
    float m0 = -1e30f, m1 = -1e30f, l0 = 0.f, l1 = 0.f;

    for (int kt = 0; kt <= qt; kt++) {
#pragma unroll
        for (int i = 0; i < 4; i++) {
            int idx = tid + i * 128;
            int r = idx >> 3, c = (idx & 7) * 8;
            *(uint4*)&Ks[r][c] = *(const uint4*)(kp + (size_t)(kt*64 + r) * 64 + c);
            *(uint4*)&Vs[r][c] = *(const uint4*)(vp + (size_t)(kt*64 + r) * 64 + c);
        }
        __syncthreads();

        // S = Q @ K^T   (Q pre-scaled)
        float sacc[8][4];
#pragma unroll
        for (int t = 0; t < 8; t++)
#pragma unroll
            for (int e = 0; e < 4; e++) sacc[t][e] = 0.f;

#pragma unroll
        for (int j = 0; j < 4; j++) {
            uint32_t a0, a1, a2, a3;
            ldsm4(a0, a1, a2, a3,
                  sptr(&Qs[warp*16 + (lane & 15)][j*16 + (lane >> 4) * 8]));
#pragma unroll
            for (int tp = 0; tp < 4; tp++) {
                uint32_t b0, b1, b2, b3;
                ldsm4(b0, b1, b2, b3,
                      sptr(&Ks[tp*16 + (lane & 7) + ((lane >> 4) & 1) * 8]
                             [j*16 + ((lane >> 3) & 1) * 8]));
                mma16816(sacc[2*tp],   a0, a1, a2, a3, b0, b1);
                mma16816(sacc[2*tp+1], a0, a1, a2, a3, b2, b3);
            }
        }

        // causal mask on the diagonal tile
        if (kt == qt) {
            int qr0 = warp*16 + (lane >> 2);
#pragma unroll
            for (int t = 0; t < 8; t++) {
                int kc = t*8 + (lane & 3) * 2;
                if (kc     > qr0)     sacc[t][0] = -1e30f;
                if (kc + 1 > qr0)     sacc[t][1] = -1e30f;
                if (kc     > qr0 + 8) sacc[t][2] = -1e30f;
                if (kc + 1 > qr0 + 8) sacc[t][3] = -1e30f;
            }
        }

        // online softmax
        float t0 = -1e30f, t1 = -1e30f;
#pragma unroll
        for (int t = 0; t < 8; t++) {
            t0 = fmaxf(t0, fmaxf(sacc[t][0], sacc[t][1]));
            t1 = fmaxf(t1, fmaxf(sacc[t][2], sacc[t][3]));
        }
        t0 = fmaxf(t0, __shfl_xor_sync(0xFFFFFFFFu, t0, 1));
        t0 = fmaxf(t0, __shfl_xor_sync(0xFFFFFFFFu, t0, 2));
        t1 = fmaxf(t1, __shfl_xor_sync(0xFFFFFFFFu, t1, 1));
        t1 = fmaxf(t1, __shfl_xor_sync(0xFFFFFFFFu, t1, 2));
        float nm0 = fmaxf(m0, t0), nm1 = fmaxf(m1, t1);
        float al0 = __expf(m0 - nm0), al1 = __expf(m1 - nm1);
        m0 = nm0; m1 = nm1;
        l0 *= al0; l1 *= al1;
#pragma unroll
        for (int t = 0; t < 8; t++) {
            sacc[t][0] = __expf(sacc[t][0] - m0);
            sacc[t][1] = __expf(sacc[t][1] - m0);
            sacc[t][2] = __expf(sacc[t][2] - m1);
            sacc[t][3] = __expf(sacc[t][3] - m1);
            l0 += sacc[t][0] + sacc[t][1];
            l1 += sacc[t][2] + sacc[t][3];
            oacc[t][0] *= al0; oacc[t][1] *= al0;
            oacc[t][2] *= al1; oacc[t][3] *= al1;
        }

        // O += P @ V   (P regs re-used directly as A fragments)
#pragma unroll
        for (int j = 0; j < 4; j++) {
            uint32_t a0 = packh2(sacc[2*j][0],   sacc[2*j][1]);
            uint32_t a1 = packh2(sacc[2*j][2],   sacc[2*j][3]);
            uint32_t a2 = packh2(sacc[2*j+1][0], sacc[2*j+1][1]);
            uint32_t a3 = packh2(sacc[2*j+1][2], sacc[2*j+1][3]);
#pragma unroll
            for (int dp = 0; dp < 4; dp++) {
                uint32_t b0, b1, b2, b3;
                ldsm4t(b0, b1, b2, b3,
                       sptr(&Vs[j*16 + (lane & 7) + ((lane >> 3) & 1) * 8]
                              [dp*16 + (lane >> 4) * 8]));
                mma16816(oacc[2*dp],   a0, a1, a2, a3, b0, b1);
                mma16816(oacc[2*dp+1], a0, a1, a2, a3, b2, b3);
            }
        }
        __syncthreads();
    }

    // finalize: O /= l, write fp16 to g_attn [b*S+s][h*64+d]
    l0 += __shfl_xor_sync(0xFFFFFFFFu, l0, 1);
    l0 += __shfl_xor_sync(0xFFFFFFFFu, l0, 2);
    l1 += __shfl_xor_sync(0xFFFFFFFFu, l1, 1);
    l1 += __shfl_xor_sync(0xFFFFFFFFu, l1, 2);
    float inv0 = 1.f / l0, inv1 = 1.f / l1;

    const int b = bh >> 4, h = bh & 15;
    const int r0 = qt*64 + warp*16 + (lane >> 2);
#pragma unroll
    for (int t = 0; t < 8; t++) {
        int col = h*64 + t*8 + (lane & 3) * 2;
        size_t base0 = ((size_t)(b * SEQ + r0))     * EMB + col;
        size_t base1 = ((size_t)(b * SEQ + r0 + 8)) * EMB + col;
        *(__half2*)(g_attn + base0) = __floats2half2_rn(oacc[t][0]*inv0, oacc[t][1]*inv0);
        *(__half2*)(g_attn + base1) = __floats2half2_rn(oacc[t][2]*inv1, oacc[t][3]*inv1);
    }
}

// ---------------- launch ----------------
extern "C" void kernel_launch(void* const* d_in, const int* in_sizes, int n_in,
                              void* d_out, int out_size) {
    (void)in_sizes; (void)n_in; (void)out_size;
    const float* x    = (const float*)d_in[0];
    const float* Wqkv = (const float*)d_in[1];
    const float* bqkv = (const float*)d_in[2];
    const float* Wo   = (const float*)d_in[3];
    const float* bo   = (const float*)d_in[4];
    // d_in[5] = mask (static tril) — causality handled analytically
    float* out = (float*)d_out;

    cvt_all<<<8192, 256>>>((const float4*)x, (const float4*)Wqkv, (const float4*)Wo);
    gemm_kernel<<<dim3(NQKV/128, ROWS/128), 256>>>(bqkv, nullptr, NQKV, 0);
    flash_kernel<<<dim3(SEQ/64, BATCH*HN), 128>>>();
    gemm_kernel<<<dim3(EMB/128, ROWS/128), 256>>>(bo, out, EMB, 1);
}

// round 14
// speedup vs baseline: 1.0059x; 1.0059x over previous
#include <cuda_runtime.h>
#include <cuda_fp16.h>
#include <stdint.h>

// Problem constants
#define EMB   1024
#define HN    16
#define HD    64
#define BATCH 2
#define SEQ   2048
#define ROWS  (BATCH*SEQ)   // 4096
#define NQKV  (3*EMB)       // 3072

// ---------------- scratch (device globals: no cudaMalloc allowed) ----------------
__device__ __align__(16) __half g_x   [ROWS*EMB];          // 8 MB
__device__ __align__(16) __half g_wqkv[EMB*NQKV];          // 6 MB
__device__ __align__(16) __half g_wo  [EMB*EMB];           // 2 MB
__device__ __align__(16) __half g_q   [BATCH*HN*SEQ*HD];   // 8 MB (pre-scaled by 0.125)
__device__ __align__(16) __half g_k   [BATCH*HN*SEQ*HD];   // 8 MB
__device__ __align__(16) __half g_v   [BATCH*HN*SEQ*HD];   // 8 MB
__device__ __align__(16) __half g_attn[ROWS*EMB];          // 8 MB  [b*S+s][h*64+d]

// ---------------- helpers ----------------
__device__ __forceinline__ uint32_t sptr(const void* p) {
    return (uint32_t)__cvta_generic_to_shared(p);
}
__device__ __forceinline__ void ldsm4(uint32_t& r0, uint32_t& r1, uint32_t& r2, uint32_t& r3, uint32_t a) {
    asm volatile("ldmatrix.sync.aligned.m8n8.x4.shared.b16 {%0,%1,%2,%3},[%4];"
                 : "=r"(r0), "=r"(r1), "=r"(r2), "=r"(r3) : "r"(a));
}
__device__ __forceinline__ void ldsm4t(uint32_t& r0, uint32_t& r1, uint32_t& r2, uint32_t& r3, uint32_t a) {
    asm volatile("ldmatrix.sync.aligned.m8n8.x4.trans.shared.b16 {%0,%1,%2,%3},[%4];"
                 : "=r"(r0), "=r"(r1), "=r"(r2), "=r"(r3) : "r"(a));
}
__device__ __forceinline__ void mma16816(float* c,
                                         uint32_t a0, uint32_t a1, uint32_t a2, uint32_t a3,
                                         uint32_t b0, uint32_t b1) {
    asm volatile("mma.sync.aligned.m16n8k16.row.col.f32.f16.f16.f32 "
                 "{%0,%1,%2,%3},{%4,%5,%6,%7},{%8,%9},{%0,%1,%2,%3};"
                 : "+f"(c[0]), "+f"(c[1]), "+f"(c[2]), "+f"(c[3])
                 : "r"(a0), "r"(a1), "r"(a2), "r"(a3), "r"(b0), "r"(b1));
}
__device__ __forceinline__ uint32_t packh2(float lo, float hi) {
    __half2 h = __floats2half2_rn(lo, hi);
    return *reinterpret_cast<uint32_t*>(&h);
}

// ---------------- fp32 -> fp16 conversion of x, W_qkv, W_o (one fused kernel) ----------------
__global__ void cvt_all(const float4* __restrict__ x,
                        const float4* __restrict__ wq,
                        const float4* __restrict__ wo) {
    const int NX = ROWS*EMB/4;      // 1048576
    const int NW = EMB*NQKV/4;      // 786432
    const int NO = EMB*EMB/4;       // 262144
    int i = blockIdx.x * blockDim.x + threadIdx.x;
    float4 v; __half2* d;
    if (i < NX)           { v = x[i];          d = (__half2*)g_x    + 2*(size_t)i; }
    else if (i < NX+NW)   { int j = i-NX;      v = wq[j]; d = (__half2*)g_wqkv + 2*(size_t)j; }
    else                  { int j = i-NX-NW;   if (j >= NO) return;
                            v = wo[j];         d = (__half2*)g_wo   + 2*(size_t)j; }
    d[0] = __floats2half2_rn(v.x, v.y);
    d[1] = __floats2half2_rn(v.z, v.w);
}

// ---------------- generic 128x128-tile GEMM (M=4096, K=1024) ----------------
// epi==0: C = x @ W_qkv + b_qkv, scattered into g_q (scaled 0.125) / g_k / g_v  (fp16)
// epi==1: C = g_attn @ W_o + b_o, written as fp32 to outF
__global__ __launch_bounds__(256) void gemm_kernel(const float* __restrict__ bias,
                                                   float* __restrict__ outF,
                                                   int N, int epi) {
    const __half* __restrict__ A  = epi ? g_attn : g_x;
    const __half* __restrict__ Bw = epi ? g_wo   : g_wqkv;

    __shared__ __align__(16) __half As[128][72];
    __shared__ __align__(16) __half Bs[64][136];

    const int tid  = threadIdx.x;
    const int lane = tid & 31;
    const int warp = tid >> 5;
    const int bm = blockIdx.y * 128;
    const int bn = blockIdx.x * 128;
    const int wm = (warp >> 1) * 32;   // 4 warps over M
    const int wn = (warp & 1) * 64;    // 2 warps over N

    float acc[2][8][4];
#pragma unroll
    for (int mt = 0; mt < 2; mt++)
#pragma unroll
        for (int nt = 0; nt < 8; nt++)
#pragma unroll
            for (int e = 0; e < 4; e++) acc[mt][nt][e] = 0.f;

    for (int kk = 0; kk < 1024; kk += 64) {
#pragma unroll
        for (int i = 0; i < 4; i++) {            // A tile: 128x64
            int idx = tid + i * 256;
            int r = idx >> 3, c = (idx & 7) * 8;
            *(uint4*)&As[r][c] = *(const uint4*)(A + (size_t)(bm + r) * 1024 + kk + c);
        }
#pragma unroll
        for (int i = 0; i < 4; i++) {            // B tile: 64x128
            int idx = tid + i * 256;
            int r = idx >> 4, c = (idx & 15) * 8;
            *(uint4*)&Bs[r][c] = *(const uint4*)(Bw + (size_t)(kk + r) * N + bn + c);
        }
        __syncthreads();

#pragma unroll
        for (int j = 0; j < 4; j++) {            // 4 k16 steps
            uint32_t a[2][4];
#pragma unroll
            for (int mt = 0; mt < 2; mt++)
                ldsm4(a[mt][0], a[mt][1], a[mt][2], a[mt][3],
                      sptr(&As[wm + mt*16 + (lane & 15)][j*16 + (lane >> 4) * 8]));
            uint32_t b[8][2];
#pragma unroll
            for (int tp = 0; tp < 4; tp++)
                ldsm4t(b[2*tp][0], b[2*tp][1], b[2*tp+1][0], b[2*tp+1][1],
                       sptr(&Bs[j*16 + (lane & 7) + ((lane >> 3) & 1) * 8]
                              [wn + tp*16 + (lane >> 4) * 8]));
#pragma unroll
            for (int mt = 0; mt < 2; mt++)
#pragma unroll
                for (int nt = 0; nt < 8; nt++)
                    mma16816(acc[mt][nt], a[mt][0], a[mt][1], a[mt][2], a[mt][3],
                             b[nt][0], b[nt][1]);
        }
        __syncthreads();
    }

    // epilogue
#pragma unroll
    for (int mt = 0; mt < 2; mt++)
#pragma unroll
        for (int nt = 0; nt < 8; nt++)
#pragma unroll
            for (int h2 = 0; h2 < 2; h2++) {
                int gr = bm + wm + mt*16 + (lane >> 2) + h2*8;
                int gc = bn + wn + nt*8 + (lane & 3) * 2;
                float v0 = acc[mt][nt][h2*2 + 0] + bias[gc];
                float v1 = acc[mt][nt][h2*2 + 1] + bias[gc + 1];
                if (epi == 0) {
                    int sec = gc >> 10;         // 0:q 1:k 2:v
                    int e   = gc & 1023;
                    if (sec == 0) { v0 *= 0.125f; v1 *= 0.125f; }  // 1/sqrt(64)
                    __half* dst = (sec == 0) ? g_q : (sec == 1 ? g_k : g_v);
                    int b = gr >> 11, s = gr & 2047;
                    int h = e >> 6,  d = e & 63;
                    size_t off = ((size_t)((b * HN + h) * SEQ + s)) * HD + d;
                    *(__half2*)(dst + off) = __floats2half2_rn(v0, v1);
                } else {
                    *(float2*)(outF + (size_t)gr * N + gc) = make_float2(v0, v1);
                }
            }
}

// ---------------- causal flash attention (FA2-style, 64 q rows / block) ----------------
__global__ __launch_bounds__(128) void flash_kernel() {
    const int qt = blockIdx.x;     // q tile (64 rows)
    const int bh = blockIdx.y;     // b*HN + h
    const __half* __restrict__ qp = g_q + (size_t)bh * SEQ * HD;
    const __half* __restrict__ kp = g_k + (size_t)bh * SEQ * HD;
    const __half* __restrict__ vp = g_v + (size_t)bh * SEQ * HD;

    __shared__ __align__(16) __half Qs[64][72];
    __shared__ __align__(16) __half Ks[64][72];
    __shared__ __align__(16) __half Vs[64][72];

    const int tid  = threadIdx.x;
    const int lane = tid & 31;
    const int warp = tid >> 5;     // each warp: 16 q rows

#pragma unroll
    for (int i = 0; i < 4; i++) {
        int idx = tid + i * 128;
        int r = idx >> 3, c = (idx & 7) * 8;
        *(uint4*)&Qs[r][c] = *(const uint4*)(qp + (size_t)(qt*64 + r) * 64 + c);
    }

    float oacc[8][4];
#pragma unroll
    for (int t = 0; t < 8; t++)
#pragma unroll
        for (int e = 0; e < 4; e++) oacc[t][e] = 0.f;
    float m0 = -1e30f, m1 = -1e30f, l0 = 0.f, l1 = 0.f;

    for (int kt = 0; kt <= qt; kt++) {
#pragma unroll
        for (int i = 0; i < 4; i++) {
            int idx = tid + i * 128;
            int r = idx >> 3, c = (idx & 7) * 8;
            *(uint4*)&Ks[r][c] = *(const uint4*)(kp + (size_t)(kt*64 + r) * 64 + c);
            *(uint4*)&Vs[r][c] = *(const uint4*)(vp + (size_t)(kt*64 + r) * 64 + c);
        }
        __syncthreads();

        // S = Q @ K^T   (Q pre-scaled)
        float sacc[8][4];
#pragma unroll
        for (int t = 0; t < 8; t++)
#pragma unroll
            for (int e = 0; e < 4; e++) sacc[t][e] = 0.f;

#pragma unroll
        for (int j = 0; j < 4; j++) {
            uint32_t a0, a1, a2, a3;
            ldsm4(a0, a1, a2, a3,
                  sptr(&Qs[warp*16 + (lane & 15)][j*16 + (lane >> 4) * 8]));
#pragma unroll
            for (int tp = 0; tp < 4; tp++) {
                uint32_t b0, b1, b2, b3;
                ldsm4(b0, b1, b2, b3,
                      sptr(&Ks[tp*16 + (lane & 7) + ((lane >> 4) & 1) * 8]
                             [j*16 + ((lane >> 3) & 1) * 8]));
                mma16816(sacc[2*tp],   a0, a1, a2, a3, b0, b1);
                mma16816(sacc[2*tp+1], a0, a1, a2, a3, b2, b3);
            }
        }

        // causal mask on the diagonal tile
        if (kt == qt) {
            int qr0 = warp*16 + (lane >> 2);
#pragma unroll
            for (int t = 0; t < 8; t++) {
                int kc = t*8 + (lane & 3) * 2;
                if (kc     > qr0)     sacc[t][0] = -1e30f;
                if (kc + 1 > qr0)     sacc[t][1] = -1e30f;
                if (kc     > qr0 + 8) sacc[t][2] = -1e30f;
                if (kc + 1 > qr0 + 8) sacc[t][3] = -1e30f;
            }
        }

        // online softmax
        float t0 = -1e30f, t1 = -1e30f;
#pragma unroll
        for (int t = 0; t < 8; t++) {
            t0 = fmaxf(t0, fmaxf(sacc[t][0], sacc[t][1]));
            t1 = fmaxf(t1, fmaxf(sacc[t][2], sacc[t][3]));
        }
        t0 = fmaxf(t0, __shfl_xor_sync(0xFFFFFFFFu, t0, 1));
        t0 = fmaxf(t0, __shfl_xor_sync(0xFFFFFFFFu, t0, 2));
        t1 = fmaxf(t1, __shfl_xor_sync(0xFFFFFFFFu, t1, 1));
        t1 = fmaxf(t1, __shfl_xor_sync(0xFFFFFFFFu, t1, 2));
        float nm0 = fmaxf(m0, t0), nm1 = fmaxf(m1, t1);
        float al0 = __expf(m0 - nm0), al1 = __expf(m1 - nm1);
        m0 = nm0; m1 = nm1;
        l0 *= al0; l1 *= al1;
#pragma unroll
        for (int t = 0; t < 8; t++) {
            sacc[t][0] = __expf(sacc[t][0] - m0);
            sacc[t][1] = __expf(sacc[t][1] - m0);
            sacc[t][2] = __expf(sacc[t][2] - m1);
            sacc[t][3] = __expf(sacc[t][3] - m1);
            l0 += sacc[t][0] + sacc[t][1];
            l1 += sacc[t][2] + sacc[t][3];
            oacc[t][0] *= al0; oacc[t][1] *= al0;
            oacc[t][2] *= al1; oacc[t][3] *= al1;
        }

        // O += P @ V   (P regs re-used directly as A fragments)
#pragma unroll
        for (int j = 0; j < 4; j++) {
            uint32_t a0 = packh2(sacc[2*j][0],   sacc[2*j][1]);
            uint32_t a1 = packh2(sacc[2*j][2],   sacc[2*j][3]);
            uint32_t a2 = packh2(sacc[2*j+1][0], sacc[2*j+1][1]);
            uint32_t a3 = packh2(sacc[2*j+1][2], sacc[2*j+1][3]);
#pragma unroll
            for (int dp = 0; dp < 4; dp++) {
                uint32_t b0, b1, b2, b3;
                ldsm4t(b0, b1, b2, b3,
                       sptr(&Vs[j*16 + (lane & 7) + ((lane >> 3) & 1) * 8]
                              [dp*16 + (lane >> 4) * 8]));
                mma16816(oacc[2*dp],   a0, a1, a2, a3, b0, b1);
                mma16816(oacc[2*dp+1], a0, a1, a2, a3, b2, b3);
            }
        }
        __syncthreads();
    }

    // finalize: O /= l, write fp16 to g_attn [b*S+s][h*64+d]
    l0 += __shfl_xor_sync(0xFFFFFFFFu, l0, 1);
    l0 += __shfl_xor_sync(0xFFFFFFFFu, l0, 2);
    l1 += __shfl_xor_sync(0xFFFFFFFFu, l1, 1);
    l1 += __shfl_xor_sync(0xFFFFFFFFu, l1, 2);
    float inv0 = 1.f / l0, inv1 = 1.f / l1;

    const int b = bh >> 4, h = bh & 15;
    const int r0 = qt*64 + warp*16 + (lane >> 2);
#pragma unroll
    for (int t = 0; t < 8; t++) {
        int col = h*64 + t*8 + (lane & 3) * 2;
        size_t base0 = ((size_t)(b * SEQ + r0))     * EMB + col;
        size_t base1 = ((size_t)(b * SEQ + r0 + 8)) * EMB + col;
        *(__half2*)(g_attn + base0) = __floats2half2_rn(oacc[t][0]*inv0, oacc[t][1]*inv0);
        *(__half2*)(g_attn + base1) = __floats2half2_rn(oacc[t][2]*inv1, oacc[t][3]*inv1);
    }
}

// ---------------- launch ----------------
extern "C" void kernel_launch(void* const* d_in, const int* in_sizes, int n_in,
                              void* d_out, int out_size) {
    (void)in_sizes; (void)n_in; (void)out_size;
    const float* x    = (const float*)d_in[0];
    const float* Wqkv = (const float*)d_in[1];
    const float* bqkv = (const float*)d_in[2];
    const float* Wo   = (const float*)d_in[3];
    const float* bo   = (const float*)d_in[4];
    // d_in[5] = mask (static tril) — causality handled analytically
    float* out = (float*)d_out;

    cvt_all<<<8192, 256>>>((const float4*)x, (const float4*)Wqkv, (const float4*)Wo);
    gemm_kernel<<<dim3(NQKV/128, ROWS/128), 256>>>(bqkv, nullptr, NQKV, 0);
    flash_kernel<<<dim3(SEQ/64, BATCH*HN), 128>>>();
    gemm_kernel<<<dim3(EMB/128, ROWS/128), 256>>>(bo, out, EMB, 1);
}

// round 15
// speedup vs baseline: 1.0075x; 1.0016x over previous
#include <cuda_runtime.h>
#include <cuda_fp16.h>
#include <stdint.h>

// Problem constants
#define EMB   1024
#define HN    16
#define HD    64
#define BATCH 2
#define SEQ   2048
#define ROWS  (BATCH*SEQ)   // 4096
#define NQKV  (3*EMB)       // 3072

// ---------------- scratch (device globals: no cudaMalloc allowed) ----------------
__device__ __align__(16) __half g_x   [ROWS*EMB];          // 8 MB
__device__ __align__(16) __half g_wqkv[EMB*NQKV];          // 6 MB
__device__ __align__(16) __half g_wo  [EMB*EMB];           // 2 MB
__device__ __align__(16) __half g_q   [BATCH*HN*SEQ*HD];   // 8 MB (pre-scaled by 0.125)
__device__ __align__(16) __half g_k   [BATCH*HN*SEQ*HD];   // 8 MB
__device__ __align__(16) __half g_v   [BATCH*HN*SEQ*HD];   // 8 MB
__device__ __align__(16) __half g_attn[ROWS*EMB];          // 8 MB  [b*S+s][h*64+d]

// ---------------- helpers ----------------
__device__ __forceinline__ uint32_t sptr(const void* p) {
    return (uint32_t)__cvta_generic_to_shared(p);
}
__device__ __forceinline__ void ldsm4(uint32_t& r0, uint32_t& r1, uint32_t& r2, uint32_t& r3, uint32_t a) {
    asm volatile("ldmatrix.sync.aligned.m8n8.x4.shared.b16 {%0,%1,%2,%3},[%4];"
                 : "=r"(r0), "=r"(r1), "=r"(r2), "=r"(r3) : "r"(a));
}
__device__ __forceinline__ void ldsm4t(uint32_t& r0, uint32_t& r1, uint32_t& r2, uint32_t& r3, uint32_t a) {
    asm volatile("ldmatrix.sync.aligned.m8n8.x4.trans.shared.b16 {%0,%1,%2,%3},[%4];"
                 : "=r"(r0), "=r"(r1), "=r"(r2), "=r"(r3) : "r"(a));
}
__device__ __forceinline__ void mma16816(float* c,
                                         uint32_t a0, uint32_t a1, uint32_t a2, uint32_t a3,
                                         uint32_t b0, uint32_t b1) {
    asm volatile("mma.sync.aligned.m16n8k16.row.col.f32.f16.f16.f32 "
                 "{%0,%1,%2,%3},{%4,%5,%6,%7},{%8,%9},{%0,%1,%2,%3};"
                 : "+f"(c[0]), "+f"(c[1]), "+f"(c[2]), "+f"(c[3])
                 : "r"(a0), "r"(a1), "r"(a2), "r"(a3), "r"(b0), "r"(b1));
}
__device__ __forceinline__ uint32_t packh2(float lo, float hi) {
    __half2 h = __floats2half2_rn(lo, hi);
    return *reinterpret_cast<uint32_t*>(&h);
}

// ---------------- fp32 -> fp16 conversion of x, W_qkv, W_o (one fused kernel) ----------------
__global__ void cvt_all(const float4* __restrict__ x,
                        const float4* __restrict__ wq,
                        const float4* __restrict__ wo) {
    const int NX = ROWS*EMB/4;      // 1048576
    const int NW = EMB*NQKV/4;      // 786432
    const int NO = EMB*EMB/4;       // 262144
    int i = blockIdx.x * blockDim.x + threadIdx.x;
    float4 v; __half2* d;
    if (i < NX)           { v = x[i];          d = (__half2*)g_x    + 2*(size_t)i; }
    else if (i < NX+NW)   { int j = i-NX;      v = wq[j]; d = (__half2*)g_wqkv + 2*(size_t)j; }
    else                  { int j = i-NX-NW;   if (j >= NO) return;
                            v = wo[j];         d = (__half2*)g_wo   + 2*(size_t)j; }
    d[0] = __floats2half2_rn(v.x, v.y);
    d[1] = __floats2half2_rn(v.z, v.w);
}

// ---------------- generic 128x128-tile GEMM (M=4096, K=1024) ----------------
// epi==0: C = x @ W_qkv + b_qkv, scattered into g_q (scaled 0.125) / g_k / g_v  (fp16)
// epi==1: C = g_attn @ W_o + b_o, written as fp32 to outF
__global__ __launch_bounds__(256) void gemm_kernel(const float* __restrict__ bias,
                                                   float* __restrict__ outF,
                                                   int N, int epi) {
    const __half* __restrict__ A  = epi ? g_attn : g_x;
    const __half* __restrict__ Bw = epi ? g_wo   : g_wqkv;

    __shared__ __align__(16) __half As[128][72];
    __shared__ __align__(16) __half Bs[64][136];

    const int tid  = threadIdx.x;
    const int lane = tid & 31;
    const int warp = tid >> 5;
    const int bm = blockIdx.y * 128;
    const int bn = blockIdx.x * 128;
    const int wm = (warp >> 1) * 32;   // 4 warps over M
    const int wn = (warp & 1) * 64;    // 2 warps over N

    float acc[2][8][4];
#pragma unroll
    for (int mt = 0; mt < 2; mt++)
#pragma unroll
        for (int nt = 0; nt < 8; nt++)
#pragma unroll
            for (int e = 0; e < 4; e++) acc[mt][nt][e] = 0.f;

    for (int kk = 0; kk < 1024; kk += 64) {
#pragma unroll
        for (int i = 0; i < 4; i++) {            // A tile: 128x64
            int idx = tid + i * 256;
            int r = idx >> 3, c = (idx & 7) * 8;
            *(uint4*)&As[r][c] = *(const uint4*)(A + (size_t)(bm + r) * 1024 + kk + c);
        }
#pragma unroll
        for (int i = 0; i < 4; i++) {            // B tile: 64x128
            int idx = tid + i * 256;
            int r = idx >> 4, c = (idx & 15) * 8;
            *(uint4*)&Bs[r][c] = *(const uint4*)(Bw + (size_t)(kk + r) * N + bn + c);
        }
        __syncthreads();

#pragma unroll
        for (int j = 0; j < 4; j++) {            // 4 k16 steps
            uint32_t a[2][4];
#pragma unroll
            for (int mt = 0; mt < 2; mt++)
                ldsm4(a[mt][0], a[mt][1], a[mt][2], a[mt][3],
                      sptr(&As[wm + mt*16 + (lane & 15)][j*16 + (lane >> 4) * 8]));
            uint32_t b[8][2];
#pragma unroll
            for (int tp = 0; tp < 4; tp++)
                ldsm4t(b[2*tp][0], b[2*tp][1], b[2*tp+1][0], b[2*tp+1][1],
                       sptr(&Bs[j*16 + (lane & 7) + ((lane >> 3) & 1) * 8]
                              [wn + tp*16 + (lane >> 4) * 8]));
#pragma unroll
            for (int mt = 0; mt < 2; mt++)
#pragma unroll
                for (int nt = 0; nt < 8; nt++)
                    mma16816(acc[mt][nt], a[mt][0], a[mt][1], a[mt][2], a[mt][3],
                             b[nt][0], b[nt][1]);
        }
        __syncthreads();
    }

    // epilogue
#pragma unroll
    for (int mt = 0; mt < 2; mt++)
#pragma unroll
        for (int nt = 0; nt < 8; nt++)
#pragma unroll
            for (int h2 = 0; h2 < 2; h2++) {
                int gr = bm + wm + mt*16 + (lane >> 2) + h2*8;
                int gc = bn + wn + nt*8 + (lane & 3) * 2;
                float v0 = acc[mt][nt][h2*2 + 0] + bias[gc];
                float v1 = acc[mt][nt][h2*2 + 1] + bias[gc + 1];
                if (epi == 0) {
                    int sec = gc >> 10;         // 0:q 1:k 2:v
                    int e   = gc & 1023;
                    if (sec == 0) { v0 *= 0.125f; v1 *= 0.125f; }  // 1/sqrt(64)
                    __half* dst = (sec == 0) ? g_q : (sec == 1 ? g_k : g_v);
                    int b = gr >> 11, s = gr & 2047;
                    int h = e >> 6,  d = e & 63;
                    size_t off = ((size_t)((b * HN + h) * SEQ + s)) * HD + d;
                    *(__half2*)(dst + off) = __floats2half2_rn(v0, v1);
                } else {
                    *(float2*)(outF + (size_t)gr * N + gc) = make_float2(v0, v1);
                }
            }
}

// ---------------- causal flash attention (FA2-style, 64 q rows / block) ----------------
__global__ __launch_bounds__(128) void flash_kernel() {
    const int qt = blockIdx.x;     // q tile (64 rows)
    const int bh = blockIdx.y;     // b*HN + h
    const __half* __restrict__ qp = g_q + (size_t)bh * SEQ * HD;
    const __half* __restrict__ kp = g_k + (size_t)bh * SEQ * HD;
    const __half* __restrict__ vp = g_v + (size_t)bh * SEQ * HD;

    __shared__ __align__(16) __half Qs[64][72];
    __shared__ __align__(16) __half Ks[64][72];
    __shared__ __align__(16) __half Vs[64][72];

    const int tid  = threadIdx.x;
    const int lane = tid & 31;
    const int warp = tid >> 5;     // each warp: 16 q rows

#pragma unroll
    for (int i = 0; i < 4; i++) {
        int idx = tid + i * 128;
        int r = idx >> 3, c = (idx & 7) * 8;
        *(uint4*)&Qs[r][c] = *(const uint4*)(qp + (size_t)(qt*64 + r) * 64 + c);
    }

    float oacc[8][4];
#pragma unroll
    for (int t = 0; t < 8; t++)
#pragma unroll
        for (int e = 0; e < 4; e++) oacc[t][e] = 0.f;
    float m0 = -1e30f, m1 = -1e30f, l0 = 0.f, l1 = 0.f;

    for (int kt = 0; kt <= qt; kt++) {
#pragma unroll
        for (int i = 0; i < 4; i++) {
            int idx = tid + i * 128;
            int r = idx >> 3, c = (idx & 7) * 8;
            *(uint4*)&Ks[r][c] = *(const uint4*)(kp + (size_t)(kt*64 + r) * 64 + c);
            *(uint4*)&Vs[r][c] = *(const uint4*)(vp + (size_t)(kt*64 + r) * 64 + c);
        }
        __syncthreads();

        // S = Q @ K^T   (Q pre-scaled)
        float sacc[8][4];
#pragma unroll
        for (int t = 0; t < 8; t++)
#pragma unroll
            for (int e = 0; e < 4; e++) sacc[t][e] = 0.f;

#pragma unroll
        for (int j = 0; j < 4; j++) {
            uint32_t a0, a1, a2, a3;
            ldsm4(a0, a1, a2, a3,
                  sptr(&Qs[warp*16 + (lane & 15)][j*16 + (lane >> 4) * 8]));
#pragma unroll
            for (int tp = 0; tp < 4; tp++) {
                uint32_t b0, b1, b2, b3;
                ldsm4(b0, b1, b2, b3,
                      sptr(&Ks[tp*16 + (lane & 7) + ((lane >> 4) & 1) * 8]
                             [j*16 + ((lane >> 3) & 1) * 8]));
                mma16816(sacc[2*tp],   a0, a1, a2, a3, b0, b1);
                mma16816(sacc[2*tp+1], a0, a1, a2, a3, b2, b3);
            }
        }

        // causal mask on the diagonal tile
        if (kt == qt) {
            int qr0 = warp*16 + (lane >> 2);
#pragma unroll
            for (int t = 0; t < 8; t++) {
                int kc = t*8 + (lane & 3) * 2;
                if (kc     > qr0)     sacc[t][0] = -1e30f;
                if (kc + 1 > qr0)     sacc[t][1] = -1e30f;
                if (kc     > qr0 + 8) sacc[t][2] = -1e30f;
                if (kc + 1 > qr0 + 8) sacc[t][3] = -1e30f;
            }
        }

        // online softmax
        float t0 = -1e30f, t1 = -1e30f;
#pragma unroll
        for (int t = 0; t < 8; t++) {
            t0 = fmaxf(t0, fmaxf(sacc[t][0], sacc[t][1]));
            t1 = fmaxf(t1, fmaxf(sacc[t][2], sacc[t][3]));
        }
        t0 = fmaxf(t0, __shfl_xor_sync(0xFFFFFFFFu, t0, 1));
        t0 = fmaxf(t0, __shfl_xor_sync(0xFFFFFFFFu, t0, 2));
        t1 = fmaxf(t1, __shfl_xor_sync(0xFFFFFFFFu, t1, 1));
        t1 = fmaxf(t1, __shfl_xor_sync(0xFFFFFFFFu, t1, 2));
        float nm0 = fmaxf(m0, t0), nm1 = fmaxf(m1, t1);
        float al0 = __expf(m0 - nm0), al1 = __expf(m1 - nm1);
        m0 = nm0; m1 = nm1;
        l0 *= al0; l1 *= al1;
#pragma unroll
        for (int t = 0; t < 8; t++) {
            sacc[t][0] = __expf(sacc[t][0] - m0);
            sacc[t][1] = __expf(sacc[t][1] - m0);
            sacc[t][2] = __expf(sacc[t][2] - m1);
            sacc[t][3] = __expf(sacc[t][3] - m1);
            l0 += sacc[t][0] + sacc[t][1];
            l1 += sacc[t][2] + sacc[t][3];
            oacc[t][0] *= al0; oacc[t][1] *= al0;
            oacc[t][2] *= al1; oacc[t][3] *= al1;
        }

        // O += P @ V   (P regs re-used directly as A fragments)
#pragma unroll
        for (int j = 0; j < 4; j++) {
            uint32_t a0 = packh2(sacc[2*j][0],   sacc[2*j][1]);
            uint32_t a1 = packh2(sacc[2*j][2],   sacc[2*j][3]);
            uint32_t a2 = packh2(sacc[2*j+1][0], sacc[2*j+1][1]);
            uint32_t a3 = packh2(sacc[2*j+1][2], sacc[2*j+1][3]);
#pragma unroll
            for (int dp = 0; dp < 4; dp++) {
                uint32_t b0, b1, b2, b3;
                ldsm4t(b0, b1, b2, b3,
                       sptr(&Vs[j*16 + (lane & 7) + ((lane >> 3) & 1) * 8]
                              [dp*16 + (lane >> 4) * 8]));
                mma16816(oacc[2*dp],   a0, a1, a2, a3, b0, b1);
                mma16816(oacc[2*dp+1], a0, a1, a2, a3, b2, b3);
            }
        }
        __syncthreads();
    }

    // finalize: O /= l, write fp16 to g_attn [b*S+s][h*64+d]
    l0 += __shfl_xor_sync(0xFFFFFFFFu, l0, 1);
    l0 += __shfl_xor_sync(0xFFFFFFFFu, l0, 2);
    l1 += __shfl_xor_sync(0xFFFFFFFFu, l1, 1);
    l1 += __shfl_xor_sync(0xFFFFFFFFu, l1, 2);
    float inv0 = 1.f / l0, inv1 = 1.f / l1;

    const int b = bh >> 4, h = bh & 15;
    const int r0 = qt*64 + warp*16 + (lane >> 2);
#pragma unroll
    for (int t = 0; t < 8; t++) {
        int col = h*64 + t*8 + (lane & 3) * 2;
        size_t base0 = ((size_t)(b * SEQ + r0))     * EMB + col;
        size_t base1 = ((size_t)(b * SEQ + r0 + 8)) * EMB + col;
        *(__half2*)(g_attn + base0) = __floats2half2_rn(oacc[t][0]*inv0, oacc[t][1]*inv0);
        *(__half2*)(g_attn + base1) = __floats2half2_rn(oacc[t][2]*inv1, oacc[t][3]*inv1);
    }
}

// ---------------- launch ----------------
extern "C" void kernel_launch(void* const* d_in, const int* in_sizes, int n_in,
                              void* d_out, int out_size) {
    (void)in_sizes; (void)n_in; (void)out_size;
    const float* x    = (const float*)d_in[0];
    const float* Wqkv = (const float*)d_in[1];
    const float* bqkv = (const float*)d_in[2];
    const float* Wo   = (const float*)d_in[3];
    const float* bo   = (const float*)d_in[4];
    // d_in[5] = mask (static tril) — causality handled analytically
    float* out = (float*)d_out;

    cvt_all<<<8192, 256>>>((const float4*)x, (const float4*)Wqkv, (const float4*)Wo);
    gemm_kernel<<<dim3(NQKV/128, ROWS/128), 256>>>(bqkv, nullptr, NQKV, 0);
    flash_kernel<<<dim3(SEQ/64, BATCH*HN), 128>>>();
    gemm_kernel<<<dim3(EMB/128, ROWS/128), 256>>>(bo, out, EMB, 1);
}